// round 7
// baseline (speedup 1.0000x reference)
#include <cuda_runtime.h>
#include <math.h>

#define N0C 200000
#define N1C 160000
#define N2C 100000

// ---------------- scratch (static device arrays; no allocation) -------------
__device__ __align__(16) float g_X [N2C * 64];   // 6.4M floats (covers N1*32 too)
__device__ __align__(16) float g_T0[N2C * 64];
__device__ __align__(16) float g_T1[N2C * 64];
__device__ double g_part[2 * 256 * 64];          // BN partials: [sum | sumsq]
__device__ float  g_scale[64];
__device__ float  g_shift[64];

// packed fp32x2 FMA (Blackwell sm_100+): d = a*b + d, lanewise IEEE fp32
#define FMA2(d, a, b) \
    asm("fma.rn.f32x2 %0, %1, %2, %0;" : "+l"(d) : "l"(a), "l"(b))

__device__ __forceinline__ unsigned long long pack_dup(float v) {
    unsigned int vi = __float_as_uint(v);
    unsigned long long r;
    asm("mov.b64 %0, {%1, %1};" : "=l"(r) : "r"(vi));
    return r;
}

// ---------------- conv1: 125 taps, Cin=1 -> Cout=32, fused relu -------------
__global__ __launch_bounds__(256) void conv1_kernel(
    const float* __restrict__ feats, const int* __restrict__ nbr,
    const float* __restrict__ W, float* __restrict__ out,
    int Nout, int Nin, int taps)
{
    __shared__ ulonglong2 Ws[125 * 8];   // (taps, 32 floats) = 8 ulonglong2/tap
    const ulonglong2* Wg = reinterpret_cast<const ulonglong2*>(W);
    for (int i = threadIdx.x; i < taps * 8; i += 256)
        Ws[i] = Wg[i];
    __syncthreads();

    int j = blockIdx.x * 256 + threadIdx.x;
    if (j >= Nout) return;

    unsigned long long acc[16];
#pragma unroll
    for (int c = 0; c < 16; c++) acc[c] = 0ull;

    for (int k = 0; k < taps; k++) {
        int idx = nbr[k * Nout + j];
        if (idx < Nin) {
            unsigned long long vp = pack_dup(feats[idx]);
#pragma unroll
            for (int m = 0; m < 8; m++) {
                ulonglong2 w = Ws[k * 8 + m];
                FMA2(acc[2 * m + 0], vp, w.x);
                FMA2(acc[2 * m + 1], vp, w.y);
            }
        }
    }
    float4* o = reinterpret_cast<float4*>(out + (size_t)j * 32);
#pragma unroll
    for (int m = 0; m < 8; m++) {
        float2 lo = *reinterpret_cast<float2*>(&acc[2 * m + 0]);
        float2 hi = *reinterpret_cast<float2*>(&acc[2 * m + 1]);
        o[m] = make_float4(fmaxf(lo.x, 0.f), fmaxf(lo.y, 0.f),
                           fmaxf(hi.x, 0.f), fmaxf(hi.y, 0.f));
    }
}

// ---------------- pipelined tiled gather-GEMM conv (f32x2) -------------------
// out[j, :] = sum_k X[nbr[k, j], :] @ W[k]   (nbr==Nin -> zero row)
// TM output rows per block, 256 threads, static smem, single-buffered tiles.
// Software pipeline: while computing tap k from smem, the gathered rows and
// weights for tap k+1 are fetched into REGISTERS (nbr indices for k+1 were
// fetched during iteration k-1; nbr for k+2 is issued now). After compute:
// sync -> STS prefetched regs -> sync. LDG latency hides under compute.
// NOTE: resubmission of the R6 kernel (container-level failure, no compile or
// runtime error surfaced; syncs are uniform, all accesses bounds-guarded).
template <int CIN, int COUT, int TM>
__global__ __launch_bounds__(256) void conv3_kernel(
    const float* __restrict__ X, const int* __restrict__ nbr,
    const float* __restrict__ W, float* __restrict__ out,
    int Nout, int Nin, int taps)
{
    constexpr int TMP = TM + 1;         // padded transposed-row stride
    constexpr int CPT = COUT / 8;       // cols per thread
    constexpr int RPT = TM / 32;        // rows per thread
    constexpr int QPR = CIN / 4;        // float4 per gathered row
    constexpr int SIT = TM * QPR / 256; // gather float4s per thread
    constexpr int WIT = (CIN * COUT) / 1024;  // W float4s per thread

    __shared__ float AsT[CIN * TMP];
    __shared__ float Ws[CIN * COUT];

    const int tid  = threadIdx.x;
    const int tcol = tid & 7;
    const int trow = tid >> 3;
    const int row0 = blockIdx.x * TM;

    // per-thread gather slot coordinates (compile-time folded)
    int rs[SIT], qs[SIT];
#pragma unroll
    for (int it = 0; it < SIT; it++) {
        int Q = tid + 256 * it;
        rs[it] = Q / QPR;
        qs[it] = Q - rs[it] * QPR;
    }

    int    nbrA[SIT];   // indices being prefetched (tap k+2)
    int    nbrB[SIT];   // indices for next gather (tap k+1)
    float4 G[SIT];      // gathered rows for next tap
    float4 Wr[WIT];     // weights for next tap

    unsigned long long acc[RPT][CPT / 2];
#pragma unroll
    for (int i = 0; i < RPT; i++)
#pragma unroll
        for (int j = 0; j < CPT / 2; j++) acc[i][j] = 0ull;

#define LOAD_NBR(kk, dst)                                                     \
    do {                                                                      \
        _Pragma("unroll")                                                     \
        for (int it = 0; it < SIT; it++) {                                    \
            int grow = row0 + rs[it];                                         \
            dst[it] = ((kk) < taps && grow < Nout)                            \
                          ? __ldg(&nbr[(size_t)(kk) * Nout + grow]) : Nin;    \
        }                                                                     \
    } while (0)

#define LOAD_GATHER(idxs)                                                     \
    do {                                                                      \
        _Pragma("unroll")                                                     \
        for (int it = 0; it < SIT; it++) {                                    \
            if (idxs[it] < Nin)                                               \
                G[it] = reinterpret_cast<const float4*>(                      \
                            X + (size_t)idxs[it] * CIN)[qs[it]];              \
            else                                                              \
                G[it] = make_float4(0.f, 0.f, 0.f, 0.f);                      \
        }                                                                     \
    } while (0)

#define LOAD_W(kk)                                                            \
    do {                                                                      \
        const float4* Wk4 =                                                   \
            reinterpret_cast<const float4*>(W + (size_t)(kk) * CIN * COUT);   \
        _Pragma("unroll")                                                     \
        for (int i = 0; i < WIT; i++) Wr[i] = Wk4[tid + 256 * i];             \
    } while (0)

#define STS_ALL()                                                             \
    do {                                                                      \
        _Pragma("unroll")                                                     \
        for (int it = 0; it < SIT; it++) {                                    \
            float4 v = G[it];                                                 \
            AsT[(4 * qs[it] + 0) * TMP + rs[it]] = v.x;                       \
            AsT[(4 * qs[it] + 1) * TMP + rs[it]] = v.y;                       \
            AsT[(4 * qs[it] + 2) * TMP + rs[it]] = v.z;                       \
            AsT[(4 * qs[it] + 3) * TMP + rs[it]] = v.w;                       \
        }                                                                     \
        _Pragma("unroll")                                                     \
        for (int i = 0; i < WIT; i++)                                         \
            reinterpret_cast<float4*>(Ws)[tid + 256 * i] = Wr[i];             \
    } while (0)

    // prologue: stage tap 0, prefetch nbr for tap 1
    LOAD_NBR(0, nbrB);
    LOAD_GATHER(nbrB);
    LOAD_W(0);
    LOAD_NBR(1, nbrB);
    STS_ALL();
    __syncthreads();

    for (int k = 0; k < taps; k++) {
        // prefetch tap k+1 (gather uses nbrB = indices of k+1), nbr for k+2
        bool more = (k + 1 < taps);   // uniform across block
        if (more) {
            LOAD_GATHER(nbrB);
            LOAD_W(k + 1);
            LOAD_NBR(k + 2, nbrA);
        }

        // compute tap k from smem
#pragma unroll 4
        for (int kk = 0; kk < CIN; kk++) {
            unsigned long long a[RPT];
#pragma unroll
            for (int i = 0; i < RPT; i++)
                a[i] = pack_dup(AsT[kk * TMP + trow * RPT + i]);
            const ulonglong2* wrow = reinterpret_cast<const ulonglong2*>(Ws + kk * COUT);
#pragma unroll
            for (int j = 0; j < CPT / 4; j++) {
                ulonglong2 w = wrow[tcol * (CPT / 4) + j];
#pragma unroll
                for (int i = 0; i < RPT; i++) {
                    FMA2(acc[i][2 * j + 0], a[i], w.x);
                    FMA2(acc[i][2 * j + 1], a[i], w.y);
                }
            }
        }
        __syncthreads();

        if (more) {
            STS_ALL();
#pragma unroll
            for (int it = 0; it < SIT; it++) nbrB[it] = nbrA[it];
        }
        __syncthreads();
    }

#undef LOAD_NBR
#undef LOAD_GATHER
#undef LOAD_W
#undef STS_ALL

    // store raw conv output (BN applied later)
#pragma unroll
    for (int i = 0; i < RPT; i++) {
        int grow = row0 + trow * RPT + i;
        if (grow < Nout) {
            float4* o = reinterpret_cast<float4*>(out + (size_t)grow * COUT);
#pragma unroll
            for (int j = 0; j < CPT / 4; j++) {
                float2 lo = *reinterpret_cast<float2*>(&acc[i][2 * j + 0]);
                float2 hi = *reinterpret_cast<float2*>(&acc[i][2 * j + 1]);
                o[tcol * (CPT / 4) + j] = make_float4(lo.x, lo.y, hi.x, hi.y);
            }
        }
    }
}

// ---------------- BN statistics: deterministic two-stage reduction ----------
template <int C>
__global__ __launch_bounds__(256) void reduce_kernel(const float* __restrict__ x, int N)
{
    constexpr int G = 256 / C;
    int c = threadIdx.x % C;
    int g = threadIdx.x / C;
    double s = 0.0, ss = 0.0;
    for (long r = (long)blockIdx.x * G + g; r < N; r += (long)gridDim.x * G) {
        double v = (double)x[r * C + c];
        s += v;
        ss += v * v;
    }
    __shared__ double sh[512];
    sh[threadIdx.x] = s;
    sh[256 + threadIdx.x] = ss;
    __syncthreads();
    if (g == 0) {
#pragma unroll
        for (int gg = 1; gg < G; gg++) {
            s  += sh[gg * C + c];
            ss += sh[256 + gg * C + c];
        }
        g_part[blockIdx.x * 64 + c] = s;
        g_part[16384 + blockIdx.x * 64 + c] = ss;
    }
}

// parallel finalize: 256 threads, G=256/C partial-groups per channel
template <int C>
__global__ __launch_bounds__(256) void finalize_kernel(
    const float* __restrict__ gam, const float* __restrict__ bet, double Ninv)
{
    constexpr int G = 256 / C;
    int c = threadIdx.x % C;
    int g = threadIdx.x / C;
    double s = 0.0, ss = 0.0;
    for (int p = g; p < 256; p += G) {
        s  += g_part[p * 64 + c];
        ss += g_part[16384 + p * 64 + c];
    }
    __shared__ double sh[512];
    sh[threadIdx.x] = s;
    sh[256 + threadIdx.x] = ss;
    __syncthreads();
    if (g == 0) {
#pragma unroll
        for (int gg = 1; gg < G; gg++) {
            s  += sh[gg * C + c];
            ss += sh[256 + gg * C + c];
        }
        double mu  = s * Ninv;
        double var = ss * Ninv - mu * mu;
        float  sc  = (float)((double)gam[c] / sqrt(var + 1e-5));
        g_scale[c] = sc;
        g_shift[c] = bet[c] - (float)mu * sc;
    }
}

// ---------------- elementwise BN apply ---------------------------------------
__global__ void ew_bn_relu_kernel(const float* __restrict__ x, float* __restrict__ y,
                                  int total, int cmask)
{
    int i = blockIdx.x * blockDim.x + threadIdx.x;
    if (i < total) {
        int c = i & cmask;
        y[i] = fmaxf(fmaf(x[i], g_scale[c], g_shift[c]), 0.f);
    }
}

__global__ void ew_bn_add_relu_kernel(const float* __restrict__ x,
                                      const float* __restrict__ res,
                                      float* __restrict__ y, int total, int cmask)
{
    int i = blockIdx.x * blockDim.x + threadIdx.x;
    if (i < total) {
        int c = i & cmask;
        y[i] = fmaxf(res[i] + fmaf(x[i], g_scale[c], g_shift[c]), 0.f);
    }
}

// ---------------- host orchestration -----------------------------------------
static void run_block32(const float* const* p, const int* nbr,
                        float* x, float* t0, float* t1)
{
    int tiles = (N1C + 127) / 128;
    int tot   = N1C * 32;
    conv3_kernel<32, 32, 128><<<tiles, 256>>>(x, nbr, p[0], t0, N1C, N1C, 27);
    reduce_kernel<32><<<256, 256>>>(t0, N1C);
    finalize_kernel<32><<<1, 256>>>(p[2], p[3], 1.0 / N1C);
    ew_bn_relu_kernel<<<(tot + 255) / 256, 256>>>(t0, t1, tot, 31);
    conv3_kernel<32, 32, 128><<<tiles, 256>>>(t1, nbr, p[1], t0, N1C, N1C, 27);
    reduce_kernel<32><<<256, 256>>>(t0, N1C);
    finalize_kernel<32><<<1, 256>>>(p[4], p[5], 1.0 / N1C);
    ew_bn_add_relu_kernel<<<(tot + 255) / 256, 256>>>(t0, x, x, tot, 31);
}

static void run_block64(const float* const* p, const int* nbr,
                        float* x, float* t0, float* scratch, float* dst)
{
    int tiles = (N2C + 63) / 64;
    int tot   = N2C * 64;
    conv3_kernel<64, 64, 64><<<tiles, 256>>>(x, nbr, p[0], t0, N2C, N2C, 27);
    reduce_kernel<64><<<256, 256>>>(t0, N2C);
    finalize_kernel<64><<<1, 256>>>(p[2], p[3], 1.0 / N2C);
    ew_bn_relu_kernel<<<(tot + 255) / 256, 256>>>(t0, scratch, tot, 63);
    conv3_kernel<64, 64, 64><<<tiles, 256>>>(scratch, nbr, p[1], t0, N2C, N2C, 27);
    reduce_kernel<64><<<256, 256>>>(t0, N2C);
    finalize_kernel<64><<<1, 256>>>(p[4], p[5], 1.0 / N2C);
    ew_bn_add_relu_kernel<<<(tot + 255) / 256, 256>>>(t0, x, dst, tot, 63);
}

extern "C" void kernel_launch(void* const* d_in, const int* in_sizes, int n_in,
                              void* d_out, int out_size)
{
    // fully stateless: no static guards, no attributes, static smem only
    float* pX;  float* pT0;  float* pT1;
    cudaGetSymbolAddress((void**)&pX,  g_X);
    cudaGetSymbolAddress((void**)&pT0, g_T0);
    cudaGetSymbolAddress((void**)&pT1, g_T1);

    const float* feats = (const float*)d_in[0];
    const float* W1    = (const float*)d_in[1];
    const float* W2    = (const float*)d_in[2];

    const int *nbr1, *nbr_e1, *nbr2, *nbr_e2;
    const float* blk[4][6];  // per block: wa, wb, g1, b1, g2, b2

    if (in_sizes[3] == 125 * N1C) {
        // dict insertion order: feats, W1, W2, nbr1, nbr_e1, nbr2, nbr_e2, blocks...
        nbr1   = (const int*)d_in[3];
        nbr_e1 = (const int*)d_in[4];
        nbr2   = (const int*)d_in[5];
        nbr_e2 = (const int*)d_in[6];
        for (int b = 0; b < 4; b++)
            for (int j = 0; j < 6; j++)
                blk[b][j] = (const float*)d_in[7 + b * 6 + j];
    } else {
        // reference signature order: feats, W1, W2, blocks..., nbr1, nbr_e1, nbr2, nbr_e2
        for (int b = 0; b < 4; b++)
            for (int j = 0; j < 6; j++)
                blk[b][j] = (const float*)d_in[3 + b * 6 + j];
        nbr1   = (const int*)d_in[27];
        nbr_e1 = (const int*)d_in[28];
        nbr2   = (const int*)d_in[29];
        nbr_e2 = (const int*)d_in[30];
    }

    // stage 1: 125-tap conv (1->32) + relu, into X
    conv1_kernel<<<(N1C + 255) / 256, 256>>>(feats, nbr1, W1, pX, N1C, N0C, 125);

    // two residual blocks at level 1 (32 ch), X updated in place
    run_block32(blk[0], nbr_e1, pX, pT0, pT1);
    run_block32(blk[1], nbr_e1, pX, pT0, pT1);

    // downsample conv (32->64), no BN/relu, into T1
    conv3_kernel<32, 64, 128><<<(N2C + 127) / 128, 256>>>(pX, nbr2, W2, pT1, N2C, N1C, 27);

    // two residual blocks at level 2 (64 ch); final one writes d_out
    run_block64(blk[2], nbr_e2, pT1, pT0, pX, pT1);
    run_block64(blk[3], nbr_e2, pT1, pT0, pX, (float*)d_out);
}

// round 9
// speedup vs baseline: 1.0015x; 1.0015x over previous
#include <cuda_runtime.h>
#include <math.h>

#define N0C 200000
#define N1C 160000
#define N2C 100000

// ---------------- scratch (static device arrays; no allocation) -------------
__device__ __align__(16) float g_X [N2C * 64];   // 6.4M floats (covers N1*32 too)
__device__ __align__(16) float g_T0[N2C * 64];
__device__ __align__(16) float g_T1[N2C * 64];
__device__ float  g_part[2 * 256 * 64];          // BN partials (fp32): [sum | sumsq]
__device__ float  g_scale[64];
__device__ float  g_shift[64];

// packed fp32x2 FMA (Blackwell sm_100+): d = a*b + d, lanewise IEEE fp32
#define FMA2(d, a, b) \
    asm("fma.rn.f32x2 %0, %1, %2, %0;" : "+l"(d) : "l"(a), "l"(b))

__device__ __forceinline__ unsigned long long pack_dup(float v) {
    unsigned int vi = __float_as_uint(v);
    unsigned long long r;
    asm("mov.b64 %0, {%1, %1};" : "=l"(r) : "r"(vi));
    return r;
}

// ---------------- conv1: 125 taps, Cin=1 -> Cout=32, fused relu -------------
__global__ __launch_bounds__(256) void conv1_kernel(
    const float* __restrict__ feats, const int* __restrict__ nbr,
    const float* __restrict__ W, float* __restrict__ out,
    int Nout, int Nin, int taps)
{
    __shared__ ulonglong2 Ws[125 * 8];   // (taps, 32 floats) = 8 ulonglong2/tap
    const ulonglong2* Wg = reinterpret_cast<const ulonglong2*>(W);
    for (int i = threadIdx.x; i < taps * 8; i += 256)
        Ws[i] = Wg[i];
    __syncthreads();

    int j = blockIdx.x * 256 + threadIdx.x;
    if (j >= Nout) return;

    unsigned long long acc[16];
#pragma unroll
    for (int c = 0; c < 16; c++) acc[c] = 0ull;

    for (int k = 0; k < taps; k++) {
        int idx = nbr[k * Nout + j];
        if (idx < Nin) {
            unsigned long long vp = pack_dup(feats[idx]);
#pragma unroll
            for (int m = 0; m < 8; m++) {
                ulonglong2 w = Ws[k * 8 + m];
                FMA2(acc[2 * m + 0], vp, w.x);
                FMA2(acc[2 * m + 1], vp, w.y);
            }
        }
    }
    float4* o = reinterpret_cast<float4*>(out + (size_t)j * 32);
#pragma unroll
    for (int m = 0; m < 8; m++) {
        float2 lo = *reinterpret_cast<float2*>(&acc[2 * m + 0]);
        float2 hi = *reinterpret_cast<float2*>(&acc[2 * m + 1]);
        o[m] = make_float4(fmaxf(lo.x, 0.f), fmaxf(lo.y, 0.f),
                           fmaxf(hi.x, 0.f), fmaxf(hi.y, 0.f));
    }
}

// ---------------- pipelined tiled gather-GEMM conv (f32x2) -------------------
// out[j, :] = sum_k X[nbr[k, j], :] @ W[k]   (nbr==Nin -> zero row)
// TM output rows per block, 256 threads, static smem, single-buffered tiles.
// Software pipeline: while computing tap k from smem, tap k+1's gathered rows
// and weights are fetched into registers (nbr indices one tap further ahead).
template <int CIN, int COUT, int TM>
__global__ __launch_bounds__(256) void conv3_kernel(
    const float* __restrict__ X, const int* __restrict__ nbr,
    const float* __restrict__ W, float* __restrict__ out,
    int Nout, int Nin, int taps)
{
    constexpr int TMP = TM + 1;         // padded transposed-row stride
    constexpr int CPT = COUT / 8;       // cols per thread
    constexpr int RPT = TM / 32;        // rows per thread
    constexpr int QPR = CIN / 4;        // float4 per gathered row
    constexpr int SIT = TM * QPR / 256; // gather float4s per thread
    constexpr int WIT = (CIN * COUT) / 1024;  // W float4s per thread

    __shared__ float AsT[CIN * TMP];
    __shared__ float Ws[CIN * COUT];

    const int tid  = threadIdx.x;
    const int tcol = tid & 7;
    const int trow = tid >> 3;
    const int row0 = blockIdx.x * TM;

    // per-thread gather slot coordinates (compile-time folded)
    int rs[SIT], qs[SIT];
#pragma unroll
    for (int it = 0; it < SIT; it++) {
        int Q = tid + 256 * it;
        rs[it] = Q / QPR;
        qs[it] = Q - rs[it] * QPR;
    }

    int    nbrA[SIT];   // indices being prefetched (tap k+2)
    int    nbrB[SIT];   // indices for next gather (tap k+1)
    float4 G[SIT];      // gathered rows for next tap
    float4 Wr[WIT];     // weights for next tap

    unsigned long long acc[RPT][CPT / 2];
#pragma unroll
    for (int i = 0; i < RPT; i++)
#pragma unroll
        for (int j = 0; j < CPT / 2; j++) acc[i][j] = 0ull;

#define LOAD_NBR(kk, dst)                                                     \
    do {                                                                      \
        _Pragma("unroll")                                                     \
        for (int it = 0; it < SIT; it++) {                                    \
            int grow = row0 + rs[it];                                         \
            dst[it] = ((kk) < taps && grow < Nout)                            \
                          ? __ldg(&nbr[(size_t)(kk) * Nout + grow]) : Nin;    \
        }                                                                     \
    } while (0)

#define LOAD_GATHER(idxs)                                                     \
    do {                                                                      \
        _Pragma("unroll")                                                     \
        for (int it = 0; it < SIT; it++) {                                    \
            if (idxs[it] < Nin)                                               \
                G[it] = reinterpret_cast<const float4*>(                      \
                            X + (size_t)idxs[it] * CIN)[qs[it]];              \
            else                                                              \
                G[it] = make_float4(0.f, 0.f, 0.f, 0.f);                      \
        }                                                                     \
    } while (0)

#define LOAD_W(kk)                                                            \
    do {                                                                      \
        const float4* Wk4 =                                                   \
            reinterpret_cast<const float4*>(W + (size_t)(kk) * CIN * COUT);   \
        _Pragma("unroll")                                                     \
        for (int i = 0; i < WIT; i++) Wr[i] = Wk4[tid + 256 * i];             \
    } while (0)

#define STS_ALL()                                                             \
    do {                                                                      \
        _Pragma("unroll")                                                     \
        for (int it = 0; it < SIT; it++) {                                    \
            float4 v = G[it];                                                 \
            AsT[(4 * qs[it] + 0) * TMP + rs[it]] = v.x;                       \
            AsT[(4 * qs[it] + 1) * TMP + rs[it]] = v.y;                       \
            AsT[(4 * qs[it] + 2) * TMP + rs[it]] = v.z;                       \
            AsT[(4 * qs[it] + 3) * TMP + rs[it]] = v.w;                       \
        }                                                                     \
        _Pragma("unroll")                                                     \
        for (int i = 0; i < WIT; i++)                                         \
            reinterpret_cast<float4*>(Ws)[tid + 256 * i] = Wr[i];             \
    } while (0)

    // prologue: stage tap 0, prefetch nbr for tap 1
    LOAD_NBR(0, nbrB);
    LOAD_GATHER(nbrB);
    LOAD_W(0);
    LOAD_NBR(1, nbrB);
    STS_ALL();
    __syncthreads();

    for (int k = 0; k < taps; k++) {
        // prefetch tap k+1 (gather uses nbrB = indices of k+1), nbr for k+2
        bool more = (k + 1 < taps);   // uniform across block
        if (more) {
            LOAD_GATHER(nbrB);
            LOAD_W(k + 1);
            LOAD_NBR(k + 2, nbrA);
        }

        // compute tap k from smem
#pragma unroll 4
        for (int kk = 0; kk < CIN; kk++) {
            unsigned long long a[RPT];
#pragma unroll
            for (int i = 0; i < RPT; i++)
                a[i] = pack_dup(AsT[kk * TMP + trow * RPT + i]);
            const ulonglong2* wrow = reinterpret_cast<const ulonglong2*>(Ws + kk * COUT);
#pragma unroll
            for (int j = 0; j < CPT / 4; j++) {
                ulonglong2 w = wrow[tcol * (CPT / 4) + j];
#pragma unroll
                for (int i = 0; i < RPT; i++) {
                    FMA2(acc[i][2 * j + 0], a[i], w.x);
                    FMA2(acc[i][2 * j + 1], a[i], w.y);
                }
            }
        }
        __syncthreads();

        if (more) {
            STS_ALL();
#pragma unroll
            for (int it = 0; it < SIT; it++) nbrB[it] = nbrA[it];
        }
        __syncthreads();
    }

#undef LOAD_NBR
#undef LOAD_GATHER
#undef LOAD_W
#undef STS_ALL

    // store raw conv output (BN applied later)
#pragma unroll
    for (int i = 0; i < RPT; i++) {
        int grow = row0 + trow * RPT + i;
        if (grow < Nout) {
            float4* o = reinterpret_cast<float4*>(out + (size_t)grow * COUT);
#pragma unroll
            for (int j = 0; j < CPT / 4; j++) {
                float2 lo = *reinterpret_cast<float2*>(&acc[i][2 * j + 0]);
                float2 hi = *reinterpret_cast<float2*>(&acc[i][2 * j + 1]);
                o[tcol * (CPT / 4) + j] = make_float4(lo.x, lo.y, hi.x, hi.y);
            }
        }
    }
}

// ---------------- BN statistics: deterministic two-stage reduction ----------
// FP32 partials (FP64 DFMA on this chip is ~18 cyc/op/SM — it was 6.6ms of
// runtime). Per-thread runs are only ~N/2048 elements of O(1) values, so fp32
// partial sums match the reference (which computes mean/var in fp32) closely.
template <int C>
__global__ __launch_bounds__(256) void reduce_kernel(const float* __restrict__ x, int N)
{
    constexpr int G = 256 / C;
    int c = threadIdx.x % C;
    int g = threadIdx.x / C;
    float s = 0.f, ss = 0.f;
    for (int r = blockIdx.x * G + g; r < N; r += gridDim.x * G) {
        float v = x[(size_t)r * C + c];
        s += v;
        ss = fmaf(v, v, ss);
    }
    __shared__ float sh[512];
    sh[threadIdx.x] = s;
    sh[256 + threadIdx.x] = ss;
    __syncthreads();
    if (g == 0) {
#pragma unroll
        for (int gg = 1; gg < G; gg++) {
            s  += sh[gg * C + c];
            ss += sh[256 + gg * C + c];
        }
        g_part[blockIdx.x * 64 + c] = s;
        g_part[16384 + blockIdx.x * 64 + c] = ss;
    }
}

// parallel finalize: 256 threads; combine 256 fp32 partials per channel in
// double (tiny: 64ch * 512 DADD total), derive scale/shift.
template <int C>
__global__ __launch_bounds__(256) void finalize_kernel(
    const float* __restrict__ gam, const float* __restrict__ bet, double Ninv)
{
    constexpr int G = 256 / C;
    int c = threadIdx.x % C;
    int g = threadIdx.x / C;
    double s = 0.0, ss = 0.0;
    for (int p = g; p < 256; p += G) {
        s  += (double)g_part[p * 64 + c];
        ss += (double)g_part[16384 + p * 64 + c];
    }
    __shared__ double sh[512];
    sh[threadIdx.x] = s;
    sh[256 + threadIdx.x] = ss;
    __syncthreads();
    if (g == 0) {
#pragma unroll
        for (int gg = 1; gg < G; gg++) {
            s  += sh[gg * C + c];
            ss += sh[256 + gg * C + c];
        }
        double mu  = s * Ninv;
        double var = ss * Ninv - mu * mu;
        float  sc  = (float)((double)gam[c] / sqrt(var + 1e-5));
        g_scale[c] = sc;
        g_shift[c] = bet[c] - (float)mu * sc;
    }
}

// ---------------- elementwise BN apply ---------------------------------------
__global__ void ew_bn_relu_kernel(const float* __restrict__ x, float* __restrict__ y,
                                  int total, int cmask)
{
    int i = blockIdx.x * blockDim.x + threadIdx.x;
    if (i < total) {
        int c = i & cmask;
        y[i] = fmaxf(fmaf(x[i], g_scale[c], g_shift[c]), 0.f);
    }
}

__global__ void ew_bn_add_relu_kernel(const float* __restrict__ x,
                                      const float* __restrict__ res,
                                      float* __restrict__ y, int total, int cmask)
{
    int i = blockIdx.x * blockDim.x + threadIdx.x;
    if (i < total) {
        int c = i & cmask;
        y[i] = fmaxf(res[i] + fmaf(x[i], g_scale[c], g_shift[c]), 0.f);
    }
}

// ---------------- host orchestration -----------------------------------------
static void run_block32(const float* const* p, const int* nbr,
                        float* x, float* t0, float* t1)
{
    int tiles = (N1C + 127) / 128;
    int tot   = N1C * 32;
    conv3_kernel<32, 32, 128><<<tiles, 256>>>(x, nbr, p[0], t0, N1C, N1C, 27);
    reduce_kernel<32><<<256, 256>>>(t0, N1C);
    finalize_kernel<32><<<1, 256>>>(p[2], p[3], 1.0 / N1C);
    ew_bn_relu_kernel<<<(tot + 255) / 256, 256>>>(t0, t1, tot, 31);
    conv3_kernel<32, 32, 128><<<tiles, 256>>>(t1, nbr, p[1], t0, N1C, N1C, 27);
    reduce_kernel<32><<<256, 256>>>(t0, N1C);
    finalize_kernel<32><<<1, 256>>>(p[4], p[5], 1.0 / N1C);
    ew_bn_add_relu_kernel<<<(tot + 255) / 256, 256>>>(t0, x, x, tot, 31);
}

static void run_block64(const float* const* p, const int* nbr,
                        float* x, float* t0, float* scratch, float* dst)
{
    int tiles = (N2C + 63) / 64;
    int tot   = N2C * 64;
    conv3_kernel<64, 64, 64><<<tiles, 256>>>(x, nbr, p[0], t0, N2C, N2C, 27);
    reduce_kernel<64><<<256, 256>>>(t0, N2C);
    finalize_kernel<64><<<1, 256>>>(p[2], p[3], 1.0 / N2C);
    ew_bn_relu_kernel<<<(tot + 255) / 256, 256>>>(t0, scratch, tot, 63);
    conv3_kernel<64, 64, 64><<<tiles, 256>>>(scratch, nbr, p[1], t0, N2C, N2C, 27);
    reduce_kernel<64><<<256, 256>>>(t0, N2C);
    finalize_kernel<64><<<1, 256>>>(p[4], p[5], 1.0 / N2C);
    ew_bn_add_relu_kernel<<<(tot + 255) / 256, 256>>>(t0, x, dst, tot, 63);
}

extern "C" void kernel_launch(void* const* d_in, const int* in_sizes, int n_in,
                              void* d_out, int out_size)
{
    // fully stateless: no static guards, no attributes, static smem only
    float* pX;  float* pT0;  float* pT1;
    cudaGetSymbolAddress((void**)&pX,  g_X);
    cudaGetSymbolAddress((void**)&pT0, g_T0);
    cudaGetSymbolAddress((void**)&pT1, g_T1);

    const float* feats = (const float*)d_in[0];
    const float* W1    = (const float*)d_in[1];
    const float* W2    = (const float*)d_in[2];

    const int *nbr1, *nbr_e1, *nbr2, *nbr_e2;
    const float* blk[4][6];  // per block: wa, wb, g1, b1, g2, b2

    if (in_sizes[3] == 125 * N1C) {
        // dict insertion order: feats, W1, W2, nbr1, nbr_e1, nbr2, nbr_e2, blocks...
        nbr1   = (const int*)d_in[3];
        nbr_e1 = (const int*)d_in[4];
        nbr2   = (const int*)d_in[5];
        nbr_e2 = (const int*)d_in[6];
        for (int b = 0; b < 4; b++)
            for (int j = 0; j < 6; j++)
                blk[b][j] = (const float*)d_in[7 + b * 6 + j];
    } else {
        // reference signature order: feats, W1, W2, blocks..., nbr1, nbr_e1, nbr2, nbr_e2
        for (int b = 0; b < 4; b++)
            for (int j = 0; j < 6; j++)
                blk[b][j] = (const float*)d_in[3 + b * 6 + j];
        nbr1   = (const int*)d_in[27];
        nbr_e1 = (const int*)d_in[28];
        nbr2   = (const int*)d_in[29];
        nbr_e2 = (const int*)d_in[30];
    }

    // stage 1: 125-tap conv (1->32) + relu, into X
    conv1_kernel<<<(N1C + 255) / 256, 256>>>(feats, nbr1, W1, pX, N1C, N0C, 125);

    // two residual blocks at level 1 (32 ch), X updated in place
    run_block32(blk[0], nbr_e1, pX, pT0, pT1);
    run_block32(blk[1], nbr_e1, pX, pT0, pT1);

    // downsample conv (32->64), no BN/relu, into T1
    conv3_kernel<32, 64, 128><<<(N2C + 127) / 128, 256>>>(pX, nbr2, W2, pT1, N2C, N1C, 27);

    // two residual blocks at level 2 (64 ch); final one writes d_out
    run_block64(blk[2], nbr_e2, pT1, pT0, pX, pT1);
    run_block64(blk[3], nbr_e2, pT1, pT0, pX, (float*)d_out);
}

// round 10
// speedup vs baseline: 1.4113x; 1.4092x over previous
#include <cuda_runtime.h>
#include <math.h>

#define N0C 200000
#define N1C 160000
#define N2C 100000

// ---------------- scratch (static device arrays; no allocation) -------------
__device__ __align__(16) float g_X [N2C * 64];   // 6.4M floats (covers N1*32 too)
__device__ __align__(16) float g_T0[N2C * 64];
__device__ __align__(16) float g_T1[N2C * 64];
__device__ float  g_part[2 * 256 * 64];          // BN partials (fp32): [sum | sumsq]
__device__ float  g_scale[64];
__device__ float  g_shift[64];

// packed fp32x2 FMA (Blackwell sm_100+): d = a*b + d, lanewise IEEE fp32
#define FMA2(d, a, b) \
    asm("fma.rn.f32x2 %0, %1, %2, %0;" : "+l"(d) : "l"(a), "l"(b))

__device__ __forceinline__ unsigned long long pack_dup(float v) {
    unsigned int vi = __float_as_uint(v);
    unsigned long long r;
    asm("mov.b64 %0, {%1, %1};" : "=l"(r) : "r"(vi));
    return r;
}

// ---------------- conv1: 125 taps, Cin=1 -> Cout=32, fused relu -------------
__global__ __launch_bounds__(256) void conv1_kernel(
    const float* __restrict__ feats, const int* __restrict__ nbr,
    const float* __restrict__ W, float* __restrict__ out,
    int Nout, int Nin, int taps)
{
    __shared__ ulonglong2 Ws[125 * 8];
    const ulonglong2* Wg = reinterpret_cast<const ulonglong2*>(W);
    for (int i = threadIdx.x; i < taps * 8; i += 256)
        Ws[i] = Wg[i];
    __syncthreads();

    int j = blockIdx.x * 256 + threadIdx.x;
    if (j >= Nout) return;

    unsigned long long acc[16];
#pragma unroll
    for (int c = 0; c < 16; c++) acc[c] = 0ull;

    for (int k = 0; k < taps; k++) {
        int idx = nbr[k * Nout + j];
        if (idx < Nin) {
            unsigned long long vp = pack_dup(feats[idx]);
#pragma unroll
            for (int m = 0; m < 8; m++) {
                ulonglong2 w = Ws[k * 8 + m];
                FMA2(acc[2 * m + 0], vp, w.x);
                FMA2(acc[2 * m + 1], vp, w.y);
            }
        }
    }
    float4* o = reinterpret_cast<float4*>(out + (size_t)j * 32);
#pragma unroll
    for (int m = 0; m < 8; m++) {
        float2 lo = *reinterpret_cast<float2*>(&acc[2 * m + 0]);
        float2 hi = *reinterpret_cast<float2*>(&acc[2 * m + 1]);
        o[m] = make_float4(fmaxf(lo.x, 0.f), fmaxf(lo.y, 0.f),
                           fmaxf(hi.x, 0.f), fmaxf(hi.y, 0.f));
    }
}

// ---------------- conv3: generic tiled gather-GEMM (32-ch configs) ----------
template <int CIN, int COUT, int TM>
__global__ __launch_bounds__(256) void conv3_kernel(
    const float* __restrict__ X, const int* __restrict__ nbr,
    const float* __restrict__ W, float* __restrict__ out,
    int Nout, int Nin, int taps)
{
    constexpr int TMP = TM + 1;
    constexpr int CPT = COUT / 8;
    constexpr int RPT = TM / 32;
    constexpr int QPR = CIN / 4;
    constexpr int SIT = TM * QPR / 256;
    constexpr int WIT = (CIN * COUT) / 1024;

    __shared__ float AsT[CIN * TMP];
    __shared__ float Ws[CIN * COUT];

    const int tid  = threadIdx.x;
    const int tcol = tid & 7;
    const int trow = tid >> 3;
    const int row0 = blockIdx.x * TM;

    int rs[SIT], qs[SIT];
#pragma unroll
    for (int it = 0; it < SIT; it++) {
        int Q = tid + 256 * it;
        rs[it] = Q / QPR;
        qs[it] = Q - rs[it] * QPR;
    }

    unsigned long long acc[RPT][CPT / 2];
#pragma unroll
    for (int i = 0; i < RPT; i++)
#pragma unroll
        for (int j = 0; j < CPT / 2; j++) acc[i][j] = 0ull;

    for (int k = 0; k < taps; k++) {
        const float4* Wk4 = reinterpret_cast<const float4*>(W + (size_t)k * CIN * COUT);
#pragma unroll
        for (int i = 0; i < WIT; i++)
            reinterpret_cast<float4*>(Ws)[tid + 256 * i] = Wk4[tid + 256 * i];

#pragma unroll
        for (int it = 0; it < SIT; it++) {
            int grow = row0 + rs[it];
            float4 v = make_float4(0.f, 0.f, 0.f, 0.f);
            if (grow < Nout) {
                int idx = nbr[(size_t)k * Nout + grow];
                if (idx < Nin)
                    v = reinterpret_cast<const float4*>(X + (size_t)idx * CIN)[qs[it]];
            }
            AsT[(4 * qs[it] + 0) * TMP + rs[it]] = v.x;
            AsT[(4 * qs[it] + 1) * TMP + rs[it]] = v.y;
            AsT[(4 * qs[it] + 2) * TMP + rs[it]] = v.z;
            AsT[(4 * qs[it] + 3) * TMP + rs[it]] = v.w;
        }
        __syncthreads();

#pragma unroll 4
        for (int kk = 0; kk < CIN; kk++) {
            unsigned long long a[RPT];
#pragma unroll
            for (int i = 0; i < RPT; i++)
                a[i] = pack_dup(AsT[kk * TMP + trow * RPT + i]);
            const ulonglong2* wrow = reinterpret_cast<const ulonglong2*>(Ws + kk * COUT);
#pragma unroll
            for (int j = 0; j < CPT / 4; j++) {
                ulonglong2 w = wrow[tcol * (CPT / 4) + j];
#pragma unroll
                for (int i = 0; i < RPT; i++) {
                    FMA2(acc[i][2 * j + 0], a[i], w.x);
                    FMA2(acc[i][2 * j + 1], a[i], w.y);
                }
            }
        }
        __syncthreads();
    }

#pragma unroll
    for (int i = 0; i < RPT; i++) {
        int grow = row0 + trow * RPT + i;
        if (grow < Nout) {
            float4* o = reinterpret_cast<float4*>(out + (size_t)grow * COUT);
#pragma unroll
            for (int j = 0; j < CPT / 4; j++) {
                float2 lo = *reinterpret_cast<float2*>(&acc[i][2 * j + 0]);
                float2 hi = *reinterpret_cast<float2*>(&acc[i][2 * j + 1]);
                o[tcol * (CPT / 4) + j] = make_float4(lo.x, lo.y, hi.x, hi.y);
            }
        }
    }
}

// ---------------- conv4: 64->64, TM=128, K-split staging ---------------------
// Register tile 4 rows x 8 cols per thread (RPT=4, CPT=8) cuts LDS-crossbar
// bytes/FMA by 40% vs conv3<64,64,64>. A-tile holds 32 of 64 input channels
// per phase (two phases per tap) so everything fits in 48KB static smem:
// AsT 32x129 floats (16512B) + Ws 64x64 (16384B) = 32896B.
// Bank math: stores (4*tcol+s)*129 + (trow+32it) -> 32 distinct banks/warp;
// A-reads kk*129 + 4*trow + i -> 4 banks x 8-way broadcast. Conflict-free.
__global__ __launch_bounds__(256) void conv4_kernel(
    const float* __restrict__ X, const int* __restrict__ nbr,
    const float* __restrict__ W, float* __restrict__ out,
    int Nout, int Nin, int taps)
{
    __shared__ float AsT[32 * 129];
    __shared__ float Ws[64 * 64];

    const int tid  = threadIdx.x;
    const int tcol = tid & 7;      // 8 column groups x 8 cols
    const int trow = tid >> 3;     // 0..31; owns rows trow*4 .. trow*4+3
    const int row0 = blockIdx.x * 128;

    unsigned long long acc[4][4];  // 4 rows x 8 cols (as f32x2)
#pragma unroll
    for (int i = 0; i < 4; i++)
#pragma unroll
        for (int j = 0; j < 4; j++) acc[i][j] = 0ull;

    for (int k = 0; k < taps; k++) {
        // neighbor indices for the 4 rows this thread stages (rows trow+32*it)
        int nidx[4];
#pragma unroll
        for (int it = 0; it < 4; it++) {
            int grow = row0 + trow + 32 * it;
            nidx[it] = (grow < Nout) ? nbr[(size_t)k * Nout + grow] : Nin;
        }

#pragma unroll
        for (int h = 0; h < 2; h++) {
            __syncthreads();   // previous compute phase done before overwrite

            // stage A half: 32 channels (h*32 .. h*32+31) for 128 rows
#pragma unroll
            for (int it = 0; it < 4; it++) {
                float4 v = make_float4(0.f, 0.f, 0.f, 0.f);
                if (nidx[it] < Nin)
                    v = reinterpret_cast<const float4*>(
                            X + (size_t)nidx[it] * 64)[h * 8 + tcol];
                int r = trow + 32 * it;
                AsT[(4 * tcol + 0) * 129 + r] = v.x;
                AsT[(4 * tcol + 1) * 129 + r] = v.y;
                AsT[(4 * tcol + 2) * 129 + r] = v.z;
                AsT[(4 * tcol + 3) * 129 + r] = v.w;
            }
            if (h == 0) {
                const float4* Wk4 =
                    reinterpret_cast<const float4*>(W + (size_t)k * 4096);
#pragma unroll
                for (int i = 0; i < 4; i++)
                    reinterpret_cast<float4*>(Ws)[tid + 256 * i] = Wk4[tid + 256 * i];
            }
            __syncthreads();

            // compute 32 kk of this half
#pragma unroll 8
            for (int kk = 0; kk < 32; kk++) {
                unsigned long long a[4];
#pragma unroll
                for (int i = 0; i < 4; i++)
                    a[i] = pack_dup(AsT[kk * 129 + trow * 4 + i]);
                const ulonglong2* wp = reinterpret_cast<const ulonglong2*>(
                    Ws + (h * 32 + kk) * 64 + tcol * 8);
                ulonglong2 wa = wp[0];
                ulonglong2 wb = wp[1];
#pragma unroll
                for (int i = 0; i < 4; i++) {
                    FMA2(acc[i][0], a[i], wa.x);
                    FMA2(acc[i][1], a[i], wa.y);
                    FMA2(acc[i][2], a[i], wb.x);
                    FMA2(acc[i][3], a[i], wb.y);
                }
            }
        }
    }

#pragma unroll
    for (int i = 0; i < 4; i++) {
        int grow = row0 + trow * 4 + i;
        if (grow < Nout) {
            float4* o = reinterpret_cast<float4*>(out + (size_t)grow * 64);
            float2 a0 = *reinterpret_cast<float2*>(&acc[i][0]);
            float2 a1 = *reinterpret_cast<float2*>(&acc[i][1]);
            float2 a2 = *reinterpret_cast<float2*>(&acc[i][2]);
            float2 a3 = *reinterpret_cast<float2*>(&acc[i][3]);
            o[tcol * 2 + 0] = make_float4(a0.x, a0.y, a1.x, a1.y);
            o[tcol * 2 + 1] = make_float4(a2.x, a2.y, a3.x, a3.y);
        }
    }
}

// ---------------- BN statistics: fp32 two-stage reduction --------------------
template <int C>
__global__ __launch_bounds__(256) void reduce_kernel(const float* __restrict__ x, int N)
{
    constexpr int G = 256 / C;
    int c = threadIdx.x % C;
    int g = threadIdx.x / C;
    float s = 0.f, ss = 0.f;
    for (int r = blockIdx.x * G + g; r < N; r += gridDim.x * G) {
        float v = x[(size_t)r * C + c];
        s += v;
        ss = fmaf(v, v, ss);
    }
    __shared__ float sh[512];
    sh[threadIdx.x] = s;
    sh[256 + threadIdx.x] = ss;
    __syncthreads();
    if (g == 0) {
#pragma unroll
        for (int gg = 1; gg < G; gg++) {
            s  += sh[gg * C + c];
            ss += sh[256 + gg * C + c];
        }
        g_part[blockIdx.x * 64 + c] = s;
        g_part[16384 + blockIdx.x * 64 + c] = ss;
    }
}

template <int C>
__global__ __launch_bounds__(256) void finalize_kernel(
    const float* __restrict__ gam, const float* __restrict__ bet, double Ninv)
{
    constexpr int G = 256 / C;
    int c = threadIdx.x % C;
    int g = threadIdx.x / C;
    double s = 0.0, ss = 0.0;
    for (int p = g; p < 256; p += G) {
        s  += (double)g_part[p * 64 + c];
        ss += (double)g_part[16384 + p * 64 + c];
    }
    __shared__ double sh[512];
    sh[threadIdx.x] = s;
    sh[256 + threadIdx.x] = ss;
    __syncthreads();
    if (g == 0) {
#pragma unroll
        for (int gg = 1; gg < G; gg++) {
            s  += sh[gg * C + c];
            ss += sh[256 + gg * C + c];
        }
        double mu  = s * Ninv;
        double var = ss * Ninv - mu * mu;
        float  sc  = (float)((double)gam[c] / sqrt(var + 1e-5));
        g_scale[c] = sc;
        g_shift[c] = bet[c] - (float)mu * sc;
    }
}

// ---------------- elementwise BN apply ---------------------------------------
__global__ void ew_bn_relu_kernel(const float* __restrict__ x, float* __restrict__ y,
                                  int total, int cmask)
{
    int i = blockIdx.x * blockDim.x + threadIdx.x;
    if (i < total) {
        int c = i & cmask;
        y[i] = fmaxf(fmaf(x[i], g_scale[c], g_shift[c]), 0.f);
    }
}

__global__ void ew_bn_add_relu_kernel(const float* __restrict__ x,
                                      const float* __restrict__ res,
                                      float* __restrict__ y, int total, int cmask)
{
    int i = blockIdx.x * blockDim.x + threadIdx.x;
    if (i < total) {
        int c = i & cmask;
        y[i] = fmaxf(res[i] + fmaf(x[i], g_scale[c], g_shift[c]), 0.f);
    }
}

// ---------------- host orchestration -----------------------------------------
static void run_block32(const float* const* p, const int* nbr,
                        float* x, float* t0, float* t1)
{
    int tiles = (N1C + 127) / 128;
    int tot   = N1C * 32;
    conv3_kernel<32, 32, 128><<<tiles, 256>>>(x, nbr, p[0], t0, N1C, N1C, 27);
    reduce_kernel<32><<<256, 256>>>(t0, N1C);
    finalize_kernel<32><<<1, 256>>>(p[2], p[3], 1.0 / N1C);
    ew_bn_relu_kernel<<<(tot + 255) / 256, 256>>>(t0, t1, tot, 31);
    conv3_kernel<32, 32, 128><<<tiles, 256>>>(t1, nbr, p[1], t0, N1C, N1C, 27);
    reduce_kernel<32><<<256, 256>>>(t0, N1C);
    finalize_kernel<32><<<1, 256>>>(p[4], p[5], 1.0 / N1C);
    ew_bn_add_relu_kernel<<<(tot + 255) / 256, 256>>>(t0, x, x, tot, 31);
}

static void run_block64(const float* const* p, const int* nbr,
                        float* x, float* t0, float* scratch, float* dst)
{
    int tiles = (N2C + 127) / 128;
    int tot   = N2C * 64;
    conv4_kernel<<<tiles, 256>>>(x, nbr, p[0], t0, N2C, N2C, 27);
    reduce_kernel<64><<<256, 256>>>(t0, N2C);
    finalize_kernel<64><<<1, 256>>>(p[2], p[3], 1.0 / N2C);
    ew_bn_relu_kernel<<<(tot + 255) / 256, 256>>>(t0, scratch, tot, 63);
    conv4_kernel<<<tiles, 256>>>(scratch, nbr, p[1], t0, N2C, N2C, 27);
    reduce_kernel<64><<<256, 256>>>(t0, N2C);
    finalize_kernel<64><<<1, 256>>>(p[4], p[5], 1.0 / N2C);
    ew_bn_add_relu_kernel<<<(tot + 255) / 256, 256>>>(t0, x, dst, tot, 63);
}

extern "C" void kernel_launch(void* const* d_in, const int* in_sizes, int n_in,
                              void* d_out, int out_size)
{
    float* pX;  float* pT0;  float* pT1;
    cudaGetSymbolAddress((void**)&pX,  g_X);
    cudaGetSymbolAddress((void**)&pT0, g_T0);
    cudaGetSymbolAddress((void**)&pT1, g_T1);

    const float* feats = (const float*)d_in[0];
    const float* W1    = (const float*)d_in[1];
    const float* W2    = (const float*)d_in[2];

    const int *nbr1, *nbr_e1, *nbr2, *nbr_e2;
    const float* blk[4][6];

    if (in_sizes[3] == 125 * N1C) {
        nbr1   = (const int*)d_in[3];
        nbr_e1 = (const int*)d_in[4];
        nbr2   = (const int*)d_in[5];
        nbr_e2 = (const int*)d_in[6];
        for (int b = 0; b < 4; b++)
            for (int j = 0; j < 6; j++)
                blk[b][j] = (const float*)d_in[7 + b * 6 + j];
    } else {
        for (int b = 0; b < 4; b++)
            for (int j = 0; j < 6; j++)
                blk[b][j] = (const float*)d_in[3 + b * 6 + j];
        nbr1   = (const int*)d_in[27];
        nbr_e1 = (const int*)d_in[28];
        nbr2   = (const int*)d_in[29];
        nbr_e2 = (const int*)d_in[30];
    }

    // stage 1: 125-tap conv (1->32) + relu, into X
    conv1_kernel<<<(N1C + 255) / 256, 256>>>(feats, nbr1, W1, pX, N1C, N0C, 125);

    // ---- block 1 first half, with the ncu PROBE at visible launch index 3 ----
    // (fixed capture window is "-s 5 -c 1"; observed mapping puts visible
    // index 3 in the captured slot). The probe is a small (8-CTA) conv4 whose
    // output region (pT1 rows 0..1023) is fully overwritten later by the
    // 32->64 conv, so d_out is unaffected and deterministic.
    {
        int tiles = (N1C + 127) / 128;
        int tot   = N1C * 32;
        conv3_kernel<32, 32, 128><<<tiles, 256>>>(pX, nbr_e1, blk[0][0], pT0, N1C, N1C, 27);
        reduce_kernel<32><<<256, 256>>>(pT0, N1C);
        conv4_kernel<<<8, 256>>>(pX, nbr_e2, blk[2][0], pT1, 1024, N2C, 27);  // PROBE
        finalize_kernel<32><<<1, 256>>>(blk[0][2], blk[0][3], 1.0 / N1C);
        ew_bn_relu_kernel<<<(tot + 255) / 256, 256>>>(pT0, pT1, tot, 31);
        conv3_kernel<32, 32, 128><<<tiles, 256>>>(pT1, nbr_e1, blk[0][1], pT0, N1C, N1C, 27);
        reduce_kernel<32><<<256, 256>>>(pT0, N1C);
        finalize_kernel<32><<<1, 256>>>(blk[0][4], blk[0][5], 1.0 / N1C);
        ew_bn_add_relu_kernel<<<(tot + 255) / 256, 256>>>(pT0, pX, pX, tot, 31);
    }

    run_block32(blk[1], nbr_e1, pX, pT0, pT1);

    // downsample conv (32->64), no BN/relu, into T1
    conv3_kernel<32, 64, 128><<<(N2C + 127) / 128, 256>>>(pX, nbr2, W2, pT1, N2C, N1C, 27);

    // two residual blocks at level 2 (64 ch); final one writes d_out
    run_block64(blk[2], nbr_e2, pT1, pT0, pX, pT1);
    run_block64(blk[3], nbr_e2, pT1, pT0, pX, (float*)d_out);
}

// round 11
// speedup vs baseline: 1.4676x; 1.0399x over previous
#include <cuda_runtime.h>
#include <math.h>

#define N0C 200000
#define N1C 160000
#define N2C 100000

// ---------------- scratch (static device arrays; no allocation) -------------
__device__ __align__(16) float g_X [N2C * 64];   // 6.4M floats (covers N1*32 too)
__device__ __align__(16) float g_T0[N2C * 64];
__device__ __align__(16) float g_T1[N2C * 64];
__device__ float  g_part[2 * 256 * 64];          // BN partials (fp32): [sum | sumsq]
__device__ float  g_scale[64];
__device__ float  g_shift[64];

// packed fp32x2 FMA (Blackwell sm_100+): d = a*b + d, lanewise IEEE fp32
#define FMA2(d, a, b) \
    asm("fma.rn.f32x2 %0, %1, %2, %0;" : "+l"(d) : "l"(a), "l"(b))

__device__ __forceinline__ unsigned long long pack_dup(float v) {
    unsigned int vi = __float_as_uint(v);
    unsigned long long r;
    asm("mov.b64 %0, {%1, %1};" : "=l"(r) : "r"(vi));
    return r;
}

// ---------------- conv1: 125 taps, Cin=1 -> Cout=32, fused relu -------------
__global__ __launch_bounds__(256) void conv1_kernel(
    const float* __restrict__ feats, const int* __restrict__ nbr,
    const float* __restrict__ W, float* __restrict__ out,
    int Nout, int Nin, int taps)
{
    __shared__ ulonglong2 Ws[125 * 8];
    const ulonglong2* Wg = reinterpret_cast<const ulonglong2*>(W);
    for (int i = threadIdx.x; i < taps * 8; i += 256)
        Ws[i] = Wg[i];
    __syncthreads();

    int j = blockIdx.x * 256 + threadIdx.x;
    if (j >= Nout) return;

    unsigned long long acc[16];
#pragma unroll
    for (int c = 0; c < 16; c++) acc[c] = 0ull;

    for (int k = 0; k < taps; k++) {
        int idx = nbr[k * Nout + j];
        if (idx < Nin) {
            unsigned long long vp = pack_dup(feats[idx]);
#pragma unroll
            for (int m = 0; m < 8; m++) {
                ulonglong2 w = Ws[k * 8 + m];
                FMA2(acc[2 * m + 0], vp, w.x);
                FMA2(acc[2 * m + 1], vp, w.y);
            }
        }
    }
    float4* o = reinterpret_cast<float4*>(out + (size_t)j * 32);
#pragma unroll
    for (int m = 0; m < 8; m++) {
        float2 lo = *reinterpret_cast<float2*>(&acc[2 * m + 0]);
        float2 hi = *reinterpret_cast<float2*>(&acc[2 * m + 1]);
        o[m] = make_float4(fmaxf(lo.x, 0.f), fmaxf(lo.y, 0.f),
                           fmaxf(hi.x, 0.f), fmaxf(hi.y, 0.f));
    }
}

// ---------------- conv3: generic tiled gather-GEMM (32->64 downsample) ------
template <int CIN, int COUT, int TM>
__global__ __launch_bounds__(256) void conv3_kernel(
    const float* __restrict__ X, const int* __restrict__ nbr,
    const float* __restrict__ W, float* __restrict__ out,
    int Nout, int Nin, int taps)
{
    constexpr int TMP = TM + 1;
    constexpr int CPT = COUT / 8;
    constexpr int RPT = TM / 32;
    constexpr int QPR = CIN / 4;
    constexpr int SIT = TM * QPR / 256;
    constexpr int WIT = (CIN * COUT) / 1024;

    __shared__ float AsT[CIN * TMP];
    __shared__ float Ws[CIN * COUT];

    const int tid  = threadIdx.x;
    const int tcol = tid & 7;
    const int trow = tid >> 3;
    const int row0 = blockIdx.x * TM;

    int rs[SIT], qs[SIT];
#pragma unroll
    for (int it = 0; it < SIT; it++) {
        int Q = tid + 256 * it;
        rs[it] = Q / QPR;
        qs[it] = Q - rs[it] * QPR;
    }

    unsigned long long acc[RPT][CPT / 2];
#pragma unroll
    for (int i = 0; i < RPT; i++)
#pragma unroll
        for (int j = 0; j < CPT / 2; j++) acc[i][j] = 0ull;

    for (int k = 0; k < taps; k++) {
        const float4* Wk4 = reinterpret_cast<const float4*>(W + (size_t)k * CIN * COUT);
#pragma unroll
        for (int i = 0; i < WIT; i++)
            reinterpret_cast<float4*>(Ws)[tid + 256 * i] = Wk4[tid + 256 * i];

#pragma unroll
        for (int it = 0; it < SIT; it++) {
            int grow = row0 + rs[it];
            float4 v = make_float4(0.f, 0.f, 0.f, 0.f);
            if (grow < Nout) {
                int idx = nbr[(size_t)k * Nout + grow];
                if (idx < Nin)
                    v = reinterpret_cast<const float4*>(X + (size_t)idx * CIN)[qs[it]];
            }
            AsT[(4 * qs[it] + 0) * TMP + rs[it]] = v.x;
            AsT[(4 * qs[it] + 1) * TMP + rs[it]] = v.y;
            AsT[(4 * qs[it] + 2) * TMP + rs[it]] = v.z;
            AsT[(4 * qs[it] + 3) * TMP + rs[it]] = v.w;
        }
        __syncthreads();

#pragma unroll 4
        for (int kk = 0; kk < CIN; kk++) {
            unsigned long long a[RPT];
#pragma unroll
            for (int i = 0; i < RPT; i++)
                a[i] = pack_dup(AsT[kk * TMP + trow * RPT + i]);
            const ulonglong2* wrow = reinterpret_cast<const ulonglong2*>(Ws + kk * COUT);
#pragma unroll
            for (int j = 0; j < CPT / 4; j++) {
                ulonglong2 w = wrow[tcol * (CPT / 4) + j];
#pragma unroll
                for (int i = 0; i < RPT; i++) {
                    FMA2(acc[i][2 * j + 0], a[i], w.x);
                    FMA2(acc[i][2 * j + 1], a[i], w.y);
                }
            }
        }
        __syncthreads();
    }

#pragma unroll
    for (int i = 0; i < RPT; i++) {
        int grow = row0 + trow * RPT + i;
        if (grow < Nout) {
            float4* o = reinterpret_cast<float4*>(out + (size_t)grow * COUT);
#pragma unroll
            for (int j = 0; j < CPT / 4; j++) {
                float2 lo = *reinterpret_cast<float2*>(&acc[i][2 * j + 0]);
                float2 hi = *reinterpret_cast<float2*>(&acc[i][2 * j + 1]);
                o[tcol * (CPT / 4) + j] = make_float4(lo.x, lo.y, hi.x, hi.y);
            }
        }
    }
}

// ---------------- conv4: 64->64, TM=128, K-split staging ---------------------
// 4 rows x 8 cols per thread; A-tile holds 32 of 64 channels per phase.
// AsT 32x129 (16512B) + Ws 64x64 (16384B) = 32896B static smem. Conflict-free.
__global__ __launch_bounds__(256) void conv4_kernel(
    const float* __restrict__ X, const int* __restrict__ nbr,
    const float* __restrict__ W, float* __restrict__ out,
    int Nout, int Nin, int taps)
{
    __shared__ float AsT[32 * 129];
    __shared__ float Ws[64 * 64];

    const int tid  = threadIdx.x;
    const int tcol = tid & 7;
    const int trow = tid >> 3;
    const int row0 = blockIdx.x * 128;

    unsigned long long acc[4][4];
#pragma unroll
    for (int i = 0; i < 4; i++)
#pragma unroll
        for (int j = 0; j < 4; j++) acc[i][j] = 0ull;

    for (int k = 0; k < taps; k++) {
        int nidx[4];
#pragma unroll
        for (int it = 0; it < 4; it++) {
            int grow = row0 + trow + 32 * it;
            nidx[it] = (grow < Nout) ? nbr[(size_t)k * Nout + grow] : Nin;
        }

#pragma unroll
        for (int h = 0; h < 2; h++) {
            __syncthreads();

#pragma unroll
            for (int it = 0; it < 4; it++) {
                float4 v = make_float4(0.f, 0.f, 0.f, 0.f);
                if (nidx[it] < Nin)
                    v = reinterpret_cast<const float4*>(
                            X + (size_t)nidx[it] * 64)[h * 8 + tcol];
                int r = trow + 32 * it;
                AsT[(4 * tcol + 0) * 129 + r] = v.x;
                AsT[(4 * tcol + 1) * 129 + r] = v.y;
                AsT[(4 * tcol + 2) * 129 + r] = v.z;
                AsT[(4 * tcol + 3) * 129 + r] = v.w;
            }
            if (h == 0) {
                const float4* Wk4 =
                    reinterpret_cast<const float4*>(W + (size_t)k * 4096);
#pragma unroll
                for (int i = 0; i < 4; i++)
                    reinterpret_cast<float4*>(Ws)[tid + 256 * i] = Wk4[tid + 256 * i];
            }
            __syncthreads();

#pragma unroll 8
            for (int kk = 0; kk < 32; kk++) {
                unsigned long long a[4];
#pragma unroll
                for (int i = 0; i < 4; i++)
                    a[i] = pack_dup(AsT[kk * 129 + trow * 4 + i]);
                const ulonglong2* wp = reinterpret_cast<const ulonglong2*>(
                    Ws + (h * 32 + kk) * 64 + tcol * 8);
                ulonglong2 wa = wp[0];
                ulonglong2 wb = wp[1];
#pragma unroll
                for (int i = 0; i < 4; i++) {
                    FMA2(acc[i][0], a[i], wa.x);
                    FMA2(acc[i][1], a[i], wa.y);
                    FMA2(acc[i][2], a[i], wb.x);
                    FMA2(acc[i][3], a[i], wb.y);
                }
            }
        }
    }

#pragma unroll
    for (int i = 0; i < 4; i++) {
        int grow = row0 + trow * 4 + i;
        if (grow < Nout) {
            float4* o = reinterpret_cast<float4*>(out + (size_t)grow * 64);
            float2 a0 = *reinterpret_cast<float2*>(&acc[i][0]);
            float2 a1 = *reinterpret_cast<float2*>(&acc[i][1]);
            float2 a2 = *reinterpret_cast<float2*>(&acc[i][2]);
            float2 a3 = *reinterpret_cast<float2*>(&acc[i][3]);
            o[tcol * 2 + 0] = make_float4(a0.x, a0.y, a1.x, a1.y);
            o[tcol * 2 + 1] = make_float4(a2.x, a2.y, a3.x, a3.y);
        }
    }
}

// ---------------- conv5: 32->32, TM=256, 4 rows x 8 cols per thread ----------
// Same bytes/FMA ratio as conv4 (6 LDS-instr per 16 FMA2).
// AsT 32x257 (32896B) + Ws 32x32 (4096B) = 36992B static smem.
// Staging: thread (scol=tid&7, srow=tid>>3) stages float4 scol of rows
// srow+32*it (it 0..7); store banks (4*scol+s + srow) mod 32 all-distinct.
// Compute: thread (tcol=tid&3, trow=tid>>2) does rows trow*4..+3, cols
// tcol*8..+7; A-reads are 8 banks x 4-way broadcast, W-reads 4x LDS.128.
__global__ __launch_bounds__(256) void conv5_kernel(
    const float* __restrict__ X, const int* __restrict__ nbr,
    const float* __restrict__ W, float* __restrict__ out,
    int Nout, int Nin, int taps)
{
    __shared__ float AsT[32 * 257];
    __shared__ float Ws[32 * 32];

    const int tid  = threadIdx.x;
    const int scol = tid & 7;
    const int srow = tid >> 3;
    const int tcol = tid & 3;
    const int trow = tid >> 2;
    const int row0 = blockIdx.x * 256;

    unsigned long long acc[4][4];
#pragma unroll
    for (int i = 0; i < 4; i++)
#pragma unroll
        for (int j = 0; j < 4; j++) acc[i][j] = 0ull;

    for (int k = 0; k < taps; k++) {
        int nidx[8];
#pragma unroll
        for (int it = 0; it < 8; it++) {
            int grow = row0 + srow + 32 * it;
            nidx[it] = (grow < Nout) ? nbr[(size_t)k * Nout + grow] : Nin;
        }

        __syncthreads();   // previous compute done before overwrite

        reinterpret_cast<float4*>(Ws)[tid] =
            reinterpret_cast<const float4*>(W + (size_t)k * 1024)[tid];
#pragma unroll
        for (int it = 0; it < 8; it++) {
            float4 v = make_float4(0.f, 0.f, 0.f, 0.f);
            if (nidx[it] < Nin)
                v = reinterpret_cast<const float4*>(X + (size_t)nidx[it] * 32)[scol];
            int r = srow + 32 * it;
            AsT[(4 * scol + 0) * 257 + r] = v.x;
            AsT[(4 * scol + 1) * 257 + r] = v.y;
            AsT[(4 * scol + 2) * 257 + r] = v.z;
            AsT[(4 * scol + 3) * 257 + r] = v.w;
        }
        __syncthreads();

#pragma unroll 8
        for (int kk = 0; kk < 32; kk++) {
            unsigned long long a[4];
#pragma unroll
            for (int i = 0; i < 4; i++)
                a[i] = pack_dup(AsT[kk * 257 + trow * 4 + i]);
            const ulonglong2* wp = reinterpret_cast<const ulonglong2*>(
                Ws + kk * 32 + tcol * 8);
            ulonglong2 wa = wp[0];
            ulonglong2 wb = wp[1];
#pragma unroll
            for (int i = 0; i < 4; i++) {
                FMA2(acc[i][0], a[i], wa.x);
                FMA2(acc[i][1], a[i], wa.y);
                FMA2(acc[i][2], a[i], wb.x);
                FMA2(acc[i][3], a[i], wb.y);
            }
        }
    }

#pragma unroll
    for (int i = 0; i < 4; i++) {
        int grow = row0 + trow * 4 + i;
        if (grow < Nout) {
            float4* o = reinterpret_cast<float4*>(out + (size_t)grow * 32);
            float2 a0 = *reinterpret_cast<float2*>(&acc[i][0]);
            float2 a1 = *reinterpret_cast<float2*>(&acc[i][1]);
            float2 a2 = *reinterpret_cast<float2*>(&acc[i][2]);
            float2 a3 = *reinterpret_cast<float2*>(&acc[i][3]);
            o[tcol * 2 + 0] = make_float4(a0.x, a0.y, a1.x, a1.y);
            o[tcol * 2 + 1] = make_float4(a2.x, a2.y, a3.x, a3.y);
        }
    }
}

// ---------------- BN statistics: fp32 two-stage reduction --------------------
template <int C>
__global__ __launch_bounds__(256) void reduce_kernel(const float* __restrict__ x, int N)
{
    constexpr int G = 256 / C;
    int c = threadIdx.x % C;
    int g = threadIdx.x / C;
    float s = 0.f, ss = 0.f;
    for (int r = blockIdx.x * G + g; r < N; r += gridDim.x * G) {
        float v = x[(size_t)r * C + c];
        s += v;
        ss = fmaf(v, v, ss);
    }
    __shared__ float sh[512];
    sh[threadIdx.x] = s;
    sh[256 + threadIdx.x] = ss;
    __syncthreads();
    if (g == 0) {
#pragma unroll
        for (int gg = 1; gg < G; gg++) {
            s  += sh[gg * C + c];
            ss += sh[256 + gg * C + c];
        }
        g_part[blockIdx.x * 64 + c] = s;
        g_part[16384 + blockIdx.x * 64 + c] = ss;
    }
}

template <int C>
__global__ __launch_bounds__(256) void finalize_kernel(
    const float* __restrict__ gam, const float* __restrict__ bet, double Ninv)
{
    constexpr int G = 256 / C;
    int c = threadIdx.x % C;
    int g = threadIdx.x / C;
    double s = 0.0, ss = 0.0;
    for (int p = g; p < 256; p += G) {
        s  += (double)g_part[p * 64 + c];
        ss += (double)g_part[16384 + p * 64 + c];
    }
    __shared__ double sh[512];
    sh[threadIdx.x] = s;
    sh[256 + threadIdx.x] = ss;
    __syncthreads();
    if (g == 0) {
#pragma unroll
        for (int gg = 1; gg < G; gg++) {
            s  += sh[gg * C + c];
            ss += sh[256 + gg * C + c];
        }
        double mu  = s * Ninv;
        double var = ss * Ninv - mu * mu;
        float  sc  = (float)((double)gam[c] / sqrt(var + 1e-5));
        g_scale[c] = sc;
        g_shift[c] = bet[c] - (float)mu * sc;
    }
}

// ---------------- elementwise BN apply ---------------------------------------
__global__ void ew_bn_relu_kernel(const float* __restrict__ x, float* __restrict__ y,
                                  int total, int cmask)
{
    int i = blockIdx.x * blockDim.x + threadIdx.x;
    if (i < total) {
        int c = i & cmask;
        y[i] = fmaxf(fmaf(x[i], g_scale[c], g_shift[c]), 0.f);
    }
}

__global__ void ew_bn_add_relu_kernel(const float* __restrict__ x,
                                      const float* __restrict__ res,
                                      float* __restrict__ y, int total, int cmask)
{
    int i = blockIdx.x * blockDim.x + threadIdx.x;
    if (i < total) {
        int c = i & cmask;
        y[i] = fmaxf(res[i] + fmaf(x[i], g_scale[c], g_shift[c]), 0.f);
    }
}

// ---------------- host orchestration -----------------------------------------
static void run_block32(const float* const* p, const int* nbr,
                        float* x, float* t0, float* t1)
{
    int tiles = (N1C + 255) / 256;
    int tot   = N1C * 32;
    conv5_kernel<<<tiles, 256>>>(x, nbr, p[0], t0, N1C, N1C, 27);
    reduce_kernel<32><<<256, 256>>>(t0, N1C);
    finalize_kernel<32><<<1, 256>>>(p[2], p[3], 1.0 / N1C);
    ew_bn_relu_kernel<<<(tot + 255) / 256, 256>>>(t0, t1, tot, 31);
    conv5_kernel<<<tiles, 256>>>(t1, nbr, p[1], t0, N1C, N1C, 27);
    reduce_kernel<32><<<256, 256>>>(t0, N1C);
    finalize_kernel<32><<<1, 256>>>(p[4], p[5], 1.0 / N1C);
    ew_bn_add_relu_kernel<<<(tot + 255) / 256, 256>>>(t0, x, x, tot, 31);
}

static void run_block64(const float* const* p, const int* nbr,
                        float* x, float* t0, float* scratch, float* dst)
{
    int tiles = (N2C + 127) / 128;
    int tot   = N2C * 64;
    conv4_kernel<<<tiles, 256>>>(x, nbr, p[0], t0, N2C, N2C, 27);
    reduce_kernel<64><<<256, 256>>>(t0, N2C);
    finalize_kernel<64><<<1, 256>>>(p[2], p[3], 1.0 / N2C);
    ew_bn_relu_kernel<<<(tot + 255) / 256, 256>>>(t0, scratch, tot, 63);
    conv4_kernel<<<tiles, 256>>>(scratch, nbr, p[1], t0, N2C, N2C, 27);
    reduce_kernel<64><<<256, 256>>>(t0, N2C);
    finalize_kernel<64><<<1, 256>>>(p[4], p[5], 1.0 / N2C);
    ew_bn_add_relu_kernel<<<(tot + 255) / 256, 256>>>(t0, x, dst, tot, 63);
}

extern "C" void kernel_launch(void* const* d_in, const int* in_sizes, int n_in,
                              void* d_out, int out_size)
{
    float* pX;  float* pT0;  float* pT1;
    cudaGetSymbolAddress((void**)&pX,  g_X);
    cudaGetSymbolAddress((void**)&pT0, g_T0);
    cudaGetSymbolAddress((void**)&pT1, g_T1);

    const float* feats = (const float*)d_in[0];
    const float* W1    = (const float*)d_in[1];
    const float* W2    = (const float*)d_in[2];

    const int *nbr1, *nbr_e1, *nbr2, *nbr_e2;
    const float* blk[4][6];

    if (in_sizes[3] == 125 * N1C) {
        nbr1   = (const int*)d_in[3];
        nbr_e1 = (const int*)d_in[4];
        nbr2   = (const int*)d_in[5];
        nbr_e2 = (const int*)d_in[6];
        for (int b = 0; b < 4; b++)
            for (int j = 0; j < 6; j++)
                blk[b][j] = (const float*)d_in[7 + b * 6 + j];
    } else {
        for (int b = 0; b < 4; b++)
            for (int j = 0; j < 6; j++)
                blk[b][j] = (const float*)d_in[3 + b * 6 + j];
        nbr1   = (const int*)d_in[27];
        nbr_e1 = (const int*)d_in[28];
        nbr2   = (const int*)d_in[29];
        nbr_e2 = (const int*)d_in[30];
    }

    // stage 1: 125-tap conv (1->32) + relu, into X
    conv1_kernel<<<(N1C + 255) / 256, 256>>>(feats, nbr1, W1, pX, N1C, N0C, 125);

    // two residual blocks at level 1 (32 ch), X updated in place
    run_block32(blk[0], nbr_e1, pX, pT0, pT1);
    run_block32(blk[1], nbr_e1, pX, pT0, pT1);

    // downsample conv (32->64), no BN/relu, into T1
    conv3_kernel<32, 64, 128><<<(N2C + 127) / 128, 256>>>(pX, nbr2, W2, pT1, N2C, N1C, 27);

    // two residual blocks at level 2 (64 ch); final one writes d_out
    run_block64(blk[2], nbr_e2, pT1, pT0, pX, pT1);
    run_block64(blk[3], nbr_e2, pT1, pT0, pX, (float*)d_out);
}